// round 9
// baseline (speedup 1.0000x reference)
#include <cuda_runtime.h>
#include <cuda_fp16.h>
#include <stdint.h>

// ---------------- problem constants ----------------
#define KDIM    41024
#define NHID    256
#define MTOT    4096          // 2048 white + 2048 black
#define NTILES  32            // m-tiles of 128 rows
#define CPT     641           // BK64 chunks per m-tile (41024/64)
#define TOTCH   (NTILES * CPT)  // 20512
#define NCTAS   148
#define WCHUNK  139           // ceil(20512/148)
#define NSLOTS  6

// GEMM tile: BM=128, BN=256, BK=64 (f16), 512 threads, double-buffered
#define BK          64
#define PITCH_U     36        // u32 per row: 32 data (64 f16) + 4 pad
#define PITCH_BY    144
#define A_U32       (128 * PITCH_U)            // 4608
#define B_U32       (256 * PITCH_U)            // 9216
#define STAGE_U32   (A_U32 + B_U32)            // 13824
#define STAGE_BYTES (STAGE_U32 * 4)            // 55296
#define A_BYTES     (A_U32 * 4)                // 18432
#define GEMM_SMEM   (2 * STAGE_BYTES)          // 110592
#define TAIL_SMEM   (512*33*4 + 32*512*4 + 32*33*4 + 32*32*4 + 256)  // ~141.7KB

// partial slots: [6][4096][256] fp32 = 25.2MB static scratch.
// Zero-initialized at module load; slots >= cnt(tile) are NEVER written,
// so they remain zero across all launches -> fixed 6-way reduce is exact.
__device__ float g_part[(size_t)NSLOTS * MTOT * NHID];

// ---------------- helpers ----------------
__device__ __forceinline__ uint32_t f2h2(float lo, float hi) {
    uint32_t r; asm("cvt.rn.f16x2.f32 %0, %1, %2;" : "=r"(r) : "f"(hi), "f"(lo)); return r;
}
__device__ __forceinline__ uint2 cvt4h(float4 v) {
    uint2 o; o.x = f2h2(v.x, v.y); o.y = f2h2(v.z, v.w); return o;
}
__device__ __forceinline__ void mma_f16(float* c, const uint32_t* a, const uint32_t* b) {
    asm volatile(
        "mma.sync.aligned.m16n8k16.row.col.f32.f16.f16.f32 "
        "{%0,%1,%2,%3}, {%4,%5,%6,%7}, {%8,%9}, {%0,%1,%2,%3};"
        : "+f"(c[0]), "+f"(c[1]), "+f"(c[2]), "+f"(c[3])
        : "r"(a[0]), "r"(a[1]), "r"(a[2]), "r"(a[3]), "r"(b[0]), "r"(b[1]));
}
__device__ __forceinline__ void ldsm_x4(uint32_t* r, uint32_t addr) {
    asm volatile("ldmatrix.sync.aligned.m8n8.x4.shared.b16 {%0,%1,%2,%3}, [%4];"
        : "=r"(r[0]), "=r"(r[1]), "=r"(r[2]), "=r"(r[3]) : "r"(addr));
}

// =====================================================================
// Kernel 1: flat-balanced GEMM. 148 CTAs; CTA c covers global chunk
// range [139c, 139c+139). A range spans <=2 m-tiles; per tile-segment
// the CTA accumulates and flushes a partial to slot=ordinal-in-tile.
// 512 threads (16 warps, 4x4). Per warp per BK=64 chunk: 64 mma.m16n8k16.
// =====================================================================
__global__ void __launch_bounds__(512, 1) nnue_gemm(
    const float* __restrict__ wf, const float* __restrict__ bfeat,
    const float* __restrict__ W_in)
{
    extern __shared__ uint32_t smem[];
    const uint32_t sbase = (uint32_t)__cvta_generic_to_shared(smem);

    const int tid = threadIdx.x;
    const int wid = tid >> 5;
    const int lane = tid & 31;
    const int lr = lane >> 2;       // 0..7
    const int lc = lane & 3;        // 0..3
    const int mw = (wid & 3) * 32;  // 4 m-warps
    const int nw = (wid >> 2) * 64; // 4 n-warps

    const int cta = blockIdx.x;
    int g0 = cta * WCHUNK;
    const int gEnd = min(g0 + WCHUNK, TOTCH);
    if (g0 >= gEnd) return;

    // ------ producer mapping: A 4 float4/thread, B 8 float4/thread ------
    const int pr = tid >> 4;        // 0..31 row base
    const int pc = tid & 15;        // float4 col 0..15 (64 floats per row)
    const int sA0 = pr * PITCH_U + 2 * pc;                 // u32 index
    const int sB0 = A_U32 + pr * PITCH_U + 2 * pc;
    const size_t QSTEP = (size_t)32 * KDIM;                // +32 rows per q
    const float* pB0 = W_in + (size_t)pr * KDIM + pc * 4;

    // ------ ldmatrix lane addresses ------
    const uint32_t aAddr = sbase + (uint32_t)(mw + (lane & 15)) * PITCH_BY
                         + (uint32_t)((lane >> 4) << 4);
    const uint32_t bAddr = sbase + A_BYTES + (uint32_t)(nw + (lane & 7)) * PITCH_BY
                         + (uint32_t)(((lane >> 3) & 3) << 4);

    float acc[2][8][4];

    // ---------------- segment loop (<=2 iterations) ----------------
    while (g0 < gEnd) {
        const int t = g0 / CPT;                       // m-tile
        const int seg_end = min(gEnd, (t + 1) * CPT);
        const int nch = seg_end - g0;
        const int kbase = g0 - t * CPT;               // first chunk within tile
        const int ordinal = cta - (t * CPT) / WCHUNK; // partial slot, 0..5

        const float* Xb = (t < 16) ? (wf + (size_t)t * 128 * KDIM)
                                   : (bfeat + (size_t)(t - 16) * 128 * KDIM);
        const float* pA0 = Xb + (size_t)pr * KDIM + pc * 4;

        #pragma unroll
        for (int i = 0; i < 2; i++)
            #pragma unroll
            for (int tt = 0; tt < 8; tt++)
                #pragma unroll
                for (int q = 0; q < 4; q++) acc[i][tt][q] = 0.0f;

        // prologue: fill stage 0 with chunk kbase
        {
            size_t k = (size_t)kbase * BK;
            #pragma unroll
            for (int q = 0; q < 4; q++)
                *(uint2*)(smem + sA0 + q * 32 * PITCH_U) = cvt4h(*(const float4*)(pA0 + q * QSTEP + k));
            #pragma unroll
            for (int q = 0; q < 8; q++)
                *(uint2*)(smem + sB0 + q * 32 * PITCH_U) = cvt4h(*(const float4*)(pB0 + q * QSTEP + k));
        }
        __syncthreads();

        for (int l = 0; l < nch; l++) {
            const int buf = l & 1;
            const bool more = (l + 1 < nch);
            const uint32_t stOff = (uint32_t)buf * STAGE_BYTES;
            const uint32_t nbU32 = (uint32_t)(buf ^ 1) * STAGE_U32;
            const size_t k2 = (size_t)(kbase + l + 1) * BK;

            // batch 1: A(4) + B(q=0,1) loads for next chunk
            float4 v0, v1, v2, v3, v4, v5;
            if (more) {
                v0 = *(const float4*)(pA0 + 0 * QSTEP + k2);
                v1 = *(const float4*)(pA0 + 1 * QSTEP + k2);
                v2 = *(const float4*)(pA0 + 2 * QSTEP + k2);
                v3 = *(const float4*)(pA0 + 3 * QSTEP + k2);
                v4 = *(const float4*)(pB0 + 0 * QSTEP + k2);
                v5 = *(const float4*)(pB0 + 1 * QSTEP + k2);
            }

            #pragma unroll
            for (int jp = 0; jp < 2; jp++) {     // 2 k-step pairs (each 32 f16)
                uint32_t aF[2][2][4];
                #pragma unroll
                for (int i = 0; i < 2; i++)
                    #pragma unroll
                    for (int js = 0; js < 2; js++)
                        ldsm_x4(aF[i][js], aAddr + stOff
                                + (uint32_t)(i * 16 * PITCH_BY + jp * 64 + js * 32));

                uint32_t bF[2][4];
                ldsm_x4(bF[0], bAddr + stOff + (uint32_t)(jp * 64));
                #pragma unroll
                for (int tt = 0; tt < 8; tt++) {
                    if (tt < 7)
                        ldsm_x4(bF[(tt + 1) & 1], bAddr + stOff
                                + (uint32_t)((tt + 1) * 8 * PITCH_BY + jp * 64));
                    const uint32_t* bf = bF[tt & 1];
                    mma_f16(acc[0][tt], aF[0][0], bf);       // k-step 2jp
                    mma_f16(acc[1][tt], aF[1][0], bf);
                    mma_f16(acc[0][tt], aF[0][1], bf + 2);   // k-step 2jp+1
                    mma_f16(acc[1][tt], aF[1][1], bf + 2);
                }

                if (jp == 0 && more) {
                    *(uint2*)(smem + nbU32 + sA0 + 0 * 32 * PITCH_U) = cvt4h(v0);
                    *(uint2*)(smem + nbU32 + sA0 + 1 * 32 * PITCH_U) = cvt4h(v1);
                    *(uint2*)(smem + nbU32 + sA0 + 2 * 32 * PITCH_U) = cvt4h(v2);
                    *(uint2*)(smem + nbU32 + sA0 + 3 * 32 * PITCH_U) = cvt4h(v3);
                    *(uint2*)(smem + nbU32 + sB0 + 0 * 32 * PITCH_U) = cvt4h(v4);
                    *(uint2*)(smem + nbU32 + sB0 + 1 * 32 * PITCH_U) = cvt4h(v5);
                    v0 = *(const float4*)(pB0 + 2 * QSTEP + k2);
                    v1 = *(const float4*)(pB0 + 3 * QSTEP + k2);
                    v2 = *(const float4*)(pB0 + 4 * QSTEP + k2);
                    v3 = *(const float4*)(pB0 + 5 * QSTEP + k2);
                    v4 = *(const float4*)(pB0 + 6 * QSTEP + k2);
                    v5 = *(const float4*)(pB0 + 7 * QSTEP + k2);
                }
            }

            if (more) {
                *(uint2*)(smem + nbU32 + sB0 + 2 * 32 * PITCH_U) = cvt4h(v0);
                *(uint2*)(smem + nbU32 + sB0 + 3 * 32 * PITCH_U) = cvt4h(v1);
                *(uint2*)(smem + nbU32 + sB0 + 4 * 32 * PITCH_U) = cvt4h(v2);
                *(uint2*)(smem + nbU32 + sB0 + 5 * 32 * PITCH_U) = cvt4h(v3);
                *(uint2*)(smem + nbU32 + sB0 + 6 * 32 * PITCH_U) = cvt4h(v4);
                *(uint2*)(smem + nbU32 + sB0 + 7 * 32 * PITCH_U) = cvt4h(v5);
            }
            __syncthreads();
        }

        // ------ flush partial for this segment ------
        float* op = g_part + ((size_t)ordinal * MTOT + (size_t)t * 128) * NHID;
        #pragma unroll
        for (int i = 0; i < 2; i++) {
            #pragma unroll
            for (int tt = 0; tt < 8; tt++) {
                int row = mw + i * 16 + lr;
                int col = nw + tt * 8 + 2 * lc;
                float2 w0 = make_float2(acc[i][tt][0], acc[i][tt][1]);
                float2 w1 = make_float2(acc[i][tt][2], acc[i][tt][3]);
                *(float2*)(op + (size_t)row * NHID + col) = w0;
                *(float2*)(op + (size_t)(row + 8) * NHID + col) = w1;
            }
        }

        g0 = seg_end;
    }
}

// =====================================================================
// Kernel 2: fixed 6-slot reduce + bias + relu + 3-layer MLP tail
// 64 blocks x 512 threads, 32 batch rows per block (warp w -> rows w, w+16)
// (64 * 32 = 2048 = full batch; white row m, black row 2048+m)
// =====================================================================
__global__ void __launch_bounds__(512) nnue_tail(
    const float* __restrict__ b_in,
    const float* __restrict__ W_h1, const float* __restrict__ b_h1,
    const float* __restrict__ W_h2, const float* __restrict__ b_h2,
    const float* __restrict__ W_out, const float* __restrict__ b_out,
    float* __restrict__ out)
{
    extern __shared__ float smem_t[];
    float* Wh1T = smem_t;                    // [512][33]
    float* c_sm = Wh1T + 512 * 33;           // [32][512]
    float* Wh2T = c_sm + 32 * 512;           // [32][33]
    float* x1s  = Wh2T + 32 * 33;            // [32][32]

    const int tid = threadIdx.x;
    const int row0 = blockIdx.x * 32;        // 0..2016

    for (int i = tid; i < 512 * 32; i += 512) {
        int o = i >> 9, j = i & 511;
        Wh1T[j * 33 + o] = W_h1[i];
    }
    for (int i = tid; i < 32 * 32; i += 512) {
        int o = i >> 5, j = i & 31;
        Wh2T[j * 33 + o] = W_h2[i];
    }
    // combined = [relu(wh), relu(bh)]: fixed 6-slot reduce (unwritten slots
    // are guaranteed-zero __device__ memory) -> 6 independent loads in flight
    for (int e = tid; e < 32 * 512; e += 512) {
        int rs = e >> 9, j = e & 511;
        int col = j & 255;
        int m = (j < 256) ? (row0 + rs) : (2048 + row0 + rs);
        size_t base = (size_t)m * NHID + col;
        float p0 = g_part[0 * (size_t)MTOT * NHID + base];
        float p1 = g_part[1 * (size_t)MTOT * NHID + base];
        float p2 = g_part[2 * (size_t)MTOT * NHID + base];
        float p3 = g_part[3 * (size_t)MTOT * NHID + base];
        float p4 = g_part[4 * (size_t)MTOT * NHID + base];
        float p5 = g_part[5 * (size_t)MTOT * NHID + base];
        float v = b_in[col] + ((p0 + p1) + (p2 + p3)) + (p4 + p5);
        c_sm[e] = fmaxf(v, 0.0f);
    }
    __syncthreads();

    const int o  = tid & 31;
    const int rs = tid >> 5;     // warp handles rows rs and rs+16

    // layer 1: [32, 512] for two rows
    float a0 = 0.f, a1 = 0.f, b0 = 0.f, b1 = 0.f;
    const float* c0 = c_sm + rs * 512;
    const float* c1 = c_sm + (rs + 16) * 512;
    #pragma unroll 4
    for (int j = 0; j < 512; j += 2) {
        float w0 = Wh1T[(j + 0) * 33 + o];
        float w1 = Wh1T[(j + 1) * 33 + o];
        a0 = fmaf(c0[j + 0], w0, a0);
        a1 = fmaf(c0[j + 1], w1, a1);
        b0 = fmaf(c1[j + 0], w0, b0);
        b1 = fmaf(c1[j + 1], w1, b1);
    }
    float bh1 = b_h1[o];
    float x1a = fmaxf(a0 + a1 + bh1, 0.0f);
    float x1b = fmaxf(b0 + b1 + bh1, 0.0f);
    x1s[rs * 32 + o] = x1a;
    x1s[(rs + 16) * 32 + o] = x1b;
    __syncwarp();

    // layer 2: [32, 32] for two rows
    float bh2 = b_h2[o];
    float ya = bh2, yb = bh2;
    #pragma unroll
    for (int j = 0; j < 32; j++) {
        float w = Wh2T[j * 33 + o];
        ya = fmaf(x1s[rs * 32 + j], w, ya);
        yb = fmaf(x1s[(rs + 16) * 32 + j], w, yb);
    }
    float x2a = fmaxf(ya, 0.0f);
    float x2b = fmaxf(yb, 0.0f);

    // output: dot + warp reduce (two rows)
    float wo = W_out[o];
    float za = x2a * wo, zb = x2b * wo;
    #pragma unroll
    for (int d = 16; d > 0; d >>= 1) {
        za += __shfl_xor_sync(0xFFFFFFFF, za, d);
        zb += __shfl_xor_sync(0xFFFFFFFF, zb, d);
    }
    if (o == 0) {
        float bo = b_out[0];
        out[row0 + rs] = za + bo;
        out[row0 + rs + 16] = zb + bo;
    }
}

// =====================================================================
extern "C" void kernel_launch(void* const* d_in, const int* in_sizes, int n_in,
                              void* d_out, int out_size) {
    const float* wf    = (const float*)d_in[0];
    const float* bfeat = (const float*)d_in[1];
    const float* W_in  = (const float*)d_in[2];
    const float* b_in  = (const float*)d_in[3];
    const float* W_h1  = (const float*)d_in[4];
    const float* b_h1  = (const float*)d_in[5];
    const float* W_h2  = (const float*)d_in[6];
    const float* b_h2  = (const float*)d_in[7];
    const float* W_out = (const float*)d_in[8];
    const float* b_out = (const float*)d_in[9];
    float* out = (float*)d_out;

    cudaFuncSetAttribute(nnue_gemm, cudaFuncAttributeMaxDynamicSharedMemorySize, GEMM_SMEM);
    cudaFuncSetAttribute(nnue_tail, cudaFuncAttributeMaxDynamicSharedMemorySize, TAIL_SMEM);

    nnue_gemm<<<NCTAS, 512, GEMM_SMEM>>>(wf, bfeat, W_in);
    nnue_tail<<<64, 512, TAIL_SMEM>>>(b_in, W_h1, b_h1, W_h2, b_h2, W_out, b_out, out);
}

// round 11
// speedup vs baseline: 1.0128x; 1.0128x over previous
#include <cuda_runtime.h>
#include <cuda_fp16.h>
#include <stdint.h>

// ---------------- problem constants ----------------
#define KDIM    41024
#define NHID    256
#define MTOT    4096          // 2048 white + 2048 black
#define NTILES  32            // m-tiles of 128 rows
#define CPT     641           // BK64 chunks per m-tile (41024/64)
#define TOTCH   (NTILES * CPT)  // 20512
#define NCTAS   148
#define WCHUNK  139           // ceil(20512/148)
#define NSLOTS  6

// GEMM tile: BM=128, BN=256, BK=64 (f16), 512 threads, double-buffered
#define BK          64
#define PITCH_U     36        // u32 per row: 32 data (64 f16) + 4 pad
#define PITCH_BY    144
#define A_U32       (128 * PITCH_U)            // 4608
#define B_U32       (256 * PITCH_U)            // 9216
#define STAGE_U32   (A_U32 + B_U32)            // 13824
#define STAGE_BYTES (STAGE_U32 * 4)            // 55296
#define A_BYTES     (A_U32 * 4)                // 18432
#define GEMM_SMEM   (2 * STAGE_BYTES)          // 110592
#define TAIL_SMEM   ((512*33 + 16*512 + 32*33 + 16*32) * 4)   // 106624

// partial slots: [6][4096][256] fp32 = 25.2MB static scratch.
// Zero-initialized at module load; slots >= cnt(tile) are NEVER written,
// so they remain zero across all launches -> fixed 6-way reduce is exact.
__device__ float g_part[(size_t)NSLOTS * MTOT * NHID];

// ---------------- helpers ----------------
__device__ __forceinline__ uint32_t f2h2(float lo, float hi) {
    uint32_t r; asm("cvt.rn.f16x2.f32 %0, %1, %2;" : "=r"(r) : "f"(hi), "f"(lo)); return r;
}
__device__ __forceinline__ uint2 cvt4h(float4 v) {
    uint2 o; o.x = f2h2(v.x, v.y); o.y = f2h2(v.z, v.w); return o;
}
__device__ __forceinline__ void mma_f16(float* c, const uint32_t* a, const uint32_t* b) {
    asm volatile(
        "mma.sync.aligned.m16n8k16.row.col.f32.f16.f16.f32 "
        "{%0,%1,%2,%3}, {%4,%5,%6,%7}, {%8,%9}, {%0,%1,%2,%3};"
        : "+f"(c[0]), "+f"(c[1]), "+f"(c[2]), "+f"(c[3])
        : "r"(a[0]), "r"(a[1]), "r"(a[2]), "r"(a[3]), "r"(b[0]), "r"(b[1]));
}
__device__ __forceinline__ void ldsm_x4(uint32_t* r, uint32_t addr) {
    asm volatile("ldmatrix.sync.aligned.m8n8.x4.shared.b16 {%0,%1,%2,%3}, [%4];"
        : "=r"(r[0]), "=r"(r[1]), "=r"(r[2]), "=r"(r[3]) : "r"(addr));
}

// =====================================================================
// Kernel 1: flat-balanced GEMM. 148 CTAs; CTA c covers global chunk
// range [139c, 139c+139). A range spans <=2 m-tiles; per tile-segment
// the CTA accumulates and flushes a partial to slot=ordinal-in-tile.
// 512 threads (16 warps, 4x4). Per warp per BK=64 chunk: 64 mma.m16n8k16.
// =====================================================================
__global__ void __launch_bounds__(512, 1) nnue_gemm(
    const float* __restrict__ wf, const float* __restrict__ bfeat,
    const float* __restrict__ W_in)
{
    extern __shared__ uint32_t smem[];
    const uint32_t sbase = (uint32_t)__cvta_generic_to_shared(smem);

    const int tid = threadIdx.x;
    const int wid = tid >> 5;
    const int lane = tid & 31;
    const int lr = lane >> 2;       // 0..7
    const int lc = lane & 3;        // 0..3
    const int mw = (wid & 3) * 32;  // 4 m-warps
    const int nw = (wid >> 2) * 64; // 4 n-warps

    const int cta = blockIdx.x;
    int g0 = cta * WCHUNK;
    const int gEnd = min(g0 + WCHUNK, TOTCH);
    if (g0 >= gEnd) return;

    // ------ producer mapping: A 4 float4/thread, B 8 float4/thread ------
    const int pr = tid >> 4;        // 0..31 row base
    const int pc = tid & 15;        // float4 col 0..15 (64 floats per row)
    const int sA0 = pr * PITCH_U + 2 * pc;                 // u32 index
    const int sB0 = A_U32 + pr * PITCH_U + 2 * pc;
    const size_t QSTEP = (size_t)32 * KDIM;                // +32 rows per q
    const float* pB0 = W_in + (size_t)pr * KDIM + pc * 4;

    // ------ ldmatrix lane addresses ------
    const uint32_t aAddr = sbase + (uint32_t)(mw + (lane & 15)) * PITCH_BY
                         + (uint32_t)((lane >> 4) << 4);
    const uint32_t bAddr = sbase + A_BYTES + (uint32_t)(nw + (lane & 7)) * PITCH_BY
                         + (uint32_t)(((lane >> 3) & 3) << 4);

    float acc[2][8][4];

    // ---------------- segment loop (<=2 iterations) ----------------
    while (g0 < gEnd) {
        const int t = g0 / CPT;                       // m-tile
        const int seg_end = min(gEnd, (t + 1) * CPT);
        const int nch = seg_end - g0;
        const int kbase = g0 - t * CPT;               // first chunk within tile
        const int ordinal = cta - (t * CPT) / WCHUNK; // partial slot, 0..5

        const float* Xb = (t < 16) ? (wf + (size_t)t * 128 * KDIM)
                                   : (bfeat + (size_t)(t - 16) * 128 * KDIM);
        const float* pA0 = Xb + (size_t)pr * KDIM + pc * 4;

        #pragma unroll
        for (int i = 0; i < 2; i++)
            #pragma unroll
            for (int tt = 0; tt < 8; tt++)
                #pragma unroll
                for (int q = 0; q < 4; q++) acc[i][tt][q] = 0.0f;

        // prologue: fill stage 0 with chunk kbase
        {
            size_t k = (size_t)kbase * BK;
            #pragma unroll
            for (int q = 0; q < 4; q++)
                *(uint2*)(smem + sA0 + q * 32 * PITCH_U) = cvt4h(*(const float4*)(pA0 + q * QSTEP + k));
            #pragma unroll
            for (int q = 0; q < 8; q++)
                *(uint2*)(smem + sB0 + q * 32 * PITCH_U) = cvt4h(*(const float4*)(pB0 + q * QSTEP + k));
        }
        __syncthreads();

        for (int l = 0; l < nch; l++) {
            const int buf = l & 1;
            const bool more = (l + 1 < nch);
            const uint32_t stOff = (uint32_t)buf * STAGE_BYTES;
            const uint32_t nbU32 = (uint32_t)(buf ^ 1) * STAGE_U32;
            const size_t k2 = (size_t)(kbase + l + 1) * BK;

            // batch 1: A(4) + B(q=0,1) loads for next chunk
            float4 v0, v1, v2, v3, v4, v5;
            if (more) {
                v0 = *(const float4*)(pA0 + 0 * QSTEP + k2);
                v1 = *(const float4*)(pA0 + 1 * QSTEP + k2);
                v2 = *(const float4*)(pA0 + 2 * QSTEP + k2);
                v3 = *(const float4*)(pA0 + 3 * QSTEP + k2);
                v4 = *(const float4*)(pB0 + 0 * QSTEP + k2);
                v5 = *(const float4*)(pB0 + 1 * QSTEP + k2);
            }

            #pragma unroll
            for (int jp = 0; jp < 2; jp++) {     // 2 k-step pairs (each 32 f16)
                uint32_t aF[2][2][4];
                #pragma unroll
                for (int i = 0; i < 2; i++)
                    #pragma unroll
                    for (int js = 0; js < 2; js++)
                        ldsm_x4(aF[i][js], aAddr + stOff
                                + (uint32_t)(i * 16 * PITCH_BY + jp * 64 + js * 32));

                uint32_t bF[2][4];
                ldsm_x4(bF[0], bAddr + stOff + (uint32_t)(jp * 64));
                #pragma unroll
                for (int tt = 0; tt < 8; tt++) {
                    if (tt < 7)
                        ldsm_x4(bF[(tt + 1) & 1], bAddr + stOff
                                + (uint32_t)((tt + 1) * 8 * PITCH_BY + jp * 64));
                    const uint32_t* bf = bF[tt & 1];
                    mma_f16(acc[0][tt], aF[0][0], bf);       // k-step 2jp
                    mma_f16(acc[1][tt], aF[1][0], bf);
                    mma_f16(acc[0][tt], aF[0][1], bf + 2);   // k-step 2jp+1
                    mma_f16(acc[1][tt], aF[1][1], bf + 2);
                }

                if (jp == 0 && more) {
                    *(uint2*)(smem + nbU32 + sA0 + 0 * 32 * PITCH_U) = cvt4h(v0);
                    *(uint2*)(smem + nbU32 + sA0 + 1 * 32 * PITCH_U) = cvt4h(v1);
                    *(uint2*)(smem + nbU32 + sA0 + 2 * 32 * PITCH_U) = cvt4h(v2);
                    *(uint2*)(smem + nbU32 + sA0 + 3 * 32 * PITCH_U) = cvt4h(v3);
                    *(uint2*)(smem + nbU32 + sB0 + 0 * 32 * PITCH_U) = cvt4h(v4);
                    *(uint2*)(smem + nbU32 + sB0 + 1 * 32 * PITCH_U) = cvt4h(v5);
                    v0 = *(const float4*)(pB0 + 2 * QSTEP + k2);
                    v1 = *(const float4*)(pB0 + 3 * QSTEP + k2);
                    v2 = *(const float4*)(pB0 + 4 * QSTEP + k2);
                    v3 = *(const float4*)(pB0 + 5 * QSTEP + k2);
                    v4 = *(const float4*)(pB0 + 6 * QSTEP + k2);
                    v5 = *(const float4*)(pB0 + 7 * QSTEP + k2);
                }
            }

            if (more) {
                *(uint2*)(smem + nbU32 + sB0 + 2 * 32 * PITCH_U) = cvt4h(v0);
                *(uint2*)(smem + nbU32 + sB0 + 3 * 32 * PITCH_U) = cvt4h(v1);
                *(uint2*)(smem + nbU32 + sB0 + 4 * 32 * PITCH_U) = cvt4h(v2);
                *(uint2*)(smem + nbU32 + sB0 + 5 * 32 * PITCH_U) = cvt4h(v3);
                *(uint2*)(smem + nbU32 + sB0 + 6 * 32 * PITCH_U) = cvt4h(v4);
                *(uint2*)(smem + nbU32 + sB0 + 7 * 32 * PITCH_U) = cvt4h(v5);
            }
            __syncthreads();
        }

        // ------ flush partial for this segment ------
        float* op = g_part + ((size_t)ordinal * MTOT + (size_t)t * 128) * NHID;
        #pragma unroll
        for (int i = 0; i < 2; i++) {
            #pragma unroll
            for (int tt = 0; tt < 8; tt++) {
                int row = mw + i * 16 + lr;
                int col = nw + tt * 8 + 2 * lc;
                float2 w0 = make_float2(acc[i][tt][0], acc[i][tt][1]);
                float2 w1 = make_float2(acc[i][tt][2], acc[i][tt][3]);
                *(float2*)(op + (size_t)row * NHID + col) = w0;
                *(float2*)(op + (size_t)(row + 8) * NHID + col) = w1;
            }
        }

        g0 = seg_end;
    }
}

// =====================================================================
// Kernel 2: fixed 6-slot reduce + bias + relu + 3-layer MLP tail
// 128 blocks x 512 threads, 16 batch rows per block (warp w -> row w)
// (128 * 16 = 2048 = full batch; white row m, black row 2048+m)
// =====================================================================
__global__ void __launch_bounds__(512) nnue_tail(
    const float* __restrict__ b_in,
    const float* __restrict__ W_h1, const float* __restrict__ b_h1,
    const float* __restrict__ W_h2, const float* __restrict__ b_h2,
    const float* __restrict__ W_out, const float* __restrict__ b_out,
    float* __restrict__ out)
{
    extern __shared__ float smem_t[];
    float* Wh1T = smem_t;                    // [512][33]
    float* c_sm = Wh1T + 512 * 33;           // [16][512]
    float* Wh2T = c_sm + 16 * 512;           // [32][33]
    float* x1s  = Wh2T + 32 * 33;            // [16][32]

    const int tid = threadIdx.x;
    const int row0 = blockIdx.x * 16;        // 0..2032

    for (int i = tid; i < 512 * 32; i += 512) {
        int o = i >> 9, j = i & 511;
        Wh1T[j * 33 + o] = W_h1[i];
    }
    for (int i = tid; i < 32 * 32; i += 512) {   // 1024 elems, 2 iters
        int o = i >> 5, j = i & 31;
        Wh2T[j * 33 + o] = W_h2[i];
    }
    // combined = [relu(wh), relu(bh)]: fixed 6-slot reduce (unwritten slots
    // are guaranteed-zero __device__ memory) -> 6 independent loads in flight
    for (int e = tid; e < 16 * 512; e += 512) {
        int rs = e >> 9, j = e & 511;
        int col = j & 255;
        int m = (j < 256) ? (row0 + rs) : (2048 + row0 + rs);
        size_t base = (size_t)m * NHID + col;
        float p0 = g_part[0 * (size_t)MTOT * NHID + base];
        float p1 = g_part[1 * (size_t)MTOT * NHID + base];
        float p2 = g_part[2 * (size_t)MTOT * NHID + base];
        float p3 = g_part[3 * (size_t)MTOT * NHID + base];
        float p4 = g_part[4 * (size_t)MTOT * NHID + base];
        float p5 = g_part[5 * (size_t)MTOT * NHID + base];
        float v = b_in[col] + ((p0 + p1) + (p2 + p3)) + (p4 + p5);
        c_sm[e] = fmaxf(v, 0.0f);
    }
    __syncthreads();

    const int o  = tid & 31;
    const int rs = tid >> 5;     // warp w -> batch row rs (one row per warp)

    // layer 1: [32, 512] one row per warp, 4-way split accumulators
    float a0 = 0.f, a1 = 0.f, a2 = 0.f, a3 = 0.f;
    const float* c = c_sm + rs * 512;
    #pragma unroll 2
    for (int j = 0; j < 512; j += 4) {
        a0 = fmaf(c[j + 0], Wh1T[(j + 0) * 33 + o], a0);
        a1 = fmaf(c[j + 1], Wh1T[(j + 1) * 33 + o], a1);
        a2 = fmaf(c[j + 2], Wh1T[(j + 2) * 33 + o], a2);
        a3 = fmaf(c[j + 3], Wh1T[(j + 3) * 33 + o], a3);
    }
    float x1 = fmaxf(((a0 + a1) + (a2 + a3)) + b_h1[o], 0.0f);
    x1s[rs * 32 + o] = x1;
    __syncwarp();

    // layer 2: [32, 32]
    float acc2 = b_h2[o];
    #pragma unroll
    for (int j = 0; j < 32; j++)
        acc2 = fmaf(x1s[rs * 32 + j], Wh2T[j * 33 + o], acc2);
    float x2 = fmaxf(acc2, 0.0f);

    // output: dot + warp reduce
    float y = x2 * W_out[o];
    #pragma unroll
    for (int d = 16; d > 0; d >>= 1)
        y += __shfl_xor_sync(0xFFFFFFFF, y, d);
    if (o == 0)
        out[row0 + rs] = y + b_out[0];
}

// =====================================================================
extern "C" void kernel_launch(void* const* d_in, const int* in_sizes, int n_in,
                              void* d_out, int out_size) {
    const float* wf    = (const float*)d_in[0];
    const float* bfeat = (const float*)d_in[1];
    const float* W_in  = (const float*)d_in[2];
    const float* b_in  = (const float*)d_in[3];
    const float* W_h1  = (const float*)d_in[4];
    const float* b_h1  = (const float*)d_in[5];
    const float* W_h2  = (const float*)d_in[6];
    const float* b_h2  = (const float*)d_in[7];
    const float* W_out = (const float*)d_in[8];
    const float* b_out = (const float*)d_in[9];
    float* out = (float*)d_out;

    cudaFuncSetAttribute(nnue_gemm, cudaFuncAttributeMaxDynamicSharedMemorySize, GEMM_SMEM);
    cudaFuncSetAttribute(nnue_tail, cudaFuncAttributeMaxDynamicSharedMemorySize, TAIL_SMEM);

    nnue_gemm<<<NCTAS, 512, GEMM_SMEM>>>(wf, bfeat, W_in);
    nnue_tail<<<128, 512, TAIL_SMEM>>>(b_in, W_h1, b_h1, W_h2, b_h2, W_out, b_out, out);
}

// round 12
// speedup vs baseline: 1.0236x; 1.0106x over previous
#include <cuda_runtime.h>
#include <cuda_fp16.h>
#include <stdint.h>

// ---------------- problem constants ----------------
#define KDIM    41024
#define NHID    256
#define MTOT    4096          // 2048 white + 2048 black
#define NTILES  32            // m-tiles of 128 rows
#define CPT     641           // BK64 chunks per m-tile (41024/64)
#define TOTCH   (NTILES * CPT)  // 20512
#define NCTAS   148
#define WCHUNK  139           // ceil(20512/148)
#define NSLOTS  6

// GEMM tile: BM=128, BN=256, BK=64 (f16), 512 threads, double-buffered
#define BK          64
#define PITCH_U     36        // u32 per row: 32 data (64 f16) + 4 pad
#define PITCH_BY    144
#define A_U32       (128 * PITCH_U)            // 4608
#define B_U32       (256 * PITCH_U)            // 9216
#define STAGE_U32   (A_U32 + B_U32)            // 13824
#define STAGE_BYTES (STAGE_U32 * 4)            // 55296
#define A_BYTES     (A_U32 * 4)                // 18432
#define GEMM_SMEM   (2 * STAGE_BYTES)          // 110592
// tail smem: Wh1T[512*33] + c_sm[8*512] + Wh2T[32*33] + x1p[16*32] + x1s[8*32]
#define TAIL_SMEM   ((512*33 + 8*512 + 32*33 + 16*32 + 8*32) * 4)  // ~91KB

// partial slots: [6][4096][256] fp32 = 25.2MB static scratch.
// Zero-initialized at module load; slots >= cnt(tile) are NEVER written,
// so they remain zero across all launches -> fixed 6-way reduce is exact.
__device__ float g_part[(size_t)NSLOTS * MTOT * NHID];

// ---------------- helpers ----------------
__device__ __forceinline__ uint32_t f2h2(float lo, float hi) {
    uint32_t r; asm("cvt.rn.f16x2.f32 %0, %1, %2;" : "=r"(r) : "f"(hi), "f"(lo)); return r;
}
__device__ __forceinline__ uint2 cvt4h(float4 v) {
    uint2 o; o.x = f2h2(v.x, v.y); o.y = f2h2(v.z, v.w); return o;
}
__device__ __forceinline__ void mma_f16(float* c, const uint32_t* a, const uint32_t* b) {
    asm volatile(
        "mma.sync.aligned.m16n8k16.row.col.f32.f16.f16.f32 "
        "{%0,%1,%2,%3}, {%4,%5,%6,%7}, {%8,%9}, {%0,%1,%2,%3};"
        : "+f"(c[0]), "+f"(c[1]), "+f"(c[2]), "+f"(c[3])
        : "r"(a[0]), "r"(a[1]), "r"(a[2]), "r"(a[3]), "r"(b[0]), "r"(b[1]));
}
__device__ __forceinline__ void ldsm_x4(uint32_t* r, uint32_t addr) {
    asm volatile("ldmatrix.sync.aligned.m8n8.x4.shared.b16 {%0,%1,%2,%3}, [%4];"
        : "=r"(r[0]), "=r"(r[1]), "=r"(r[2]), "=r"(r[3]) : "r"(addr));
}

// =====================================================================
// Kernel 1: flat-balanced GEMM. 148 CTAs; CTA c covers global chunk
// range [139c, 139c+139). A range spans <=2 m-tiles; per tile-segment
// the CTA accumulates and flushes a partial to slot=ordinal-in-tile.
// 512 threads (16 warps, 4x4). Per warp per BK=64 chunk: 64 mma.m16n8k16.
// =====================================================================
__global__ void __launch_bounds__(512, 1) nnue_gemm(
    const float* __restrict__ wf, const float* __restrict__ bfeat,
    const float* __restrict__ W_in)
{
    extern __shared__ uint32_t smem[];
    const uint32_t sbase = (uint32_t)__cvta_generic_to_shared(smem);

    const int tid = threadIdx.x;
    const int wid = tid >> 5;
    const int lane = tid & 31;
    const int lr = lane >> 2;       // 0..7
    const int lc = lane & 3;        // 0..3
    const int mw = (wid & 3) * 32;  // 4 m-warps
    const int nw = (wid >> 2) * 64; // 4 n-warps

    const int cta = blockIdx.x;
    int g0 = cta * WCHUNK;
    const int gEnd = min(g0 + WCHUNK, TOTCH);
    if (g0 >= gEnd) return;

    // ------ producer mapping: A 4 float4/thread, B 8 float4/thread ------
    const int pr = tid >> 4;        // 0..31 row base
    const int pc = tid & 15;        // float4 col 0..15 (64 floats per row)
    const int sA0 = pr * PITCH_U + 2 * pc;                 // u32 index
    const int sB0 = A_U32 + pr * PITCH_U + 2 * pc;
    const size_t QSTEP = (size_t)32 * KDIM;                // +32 rows per q
    const float* pB0 = W_in + (size_t)pr * KDIM + pc * 4;

    // ------ ldmatrix lane addresses ------
    const uint32_t aAddr = sbase + (uint32_t)(mw + (lane & 15)) * PITCH_BY
                         + (uint32_t)((lane >> 4) << 4);
    const uint32_t bAddr = sbase + A_BYTES + (uint32_t)(nw + (lane & 7)) * PITCH_BY
                         + (uint32_t)(((lane >> 3) & 3) << 4);

    float acc[2][8][4];

    // ---------------- segment loop (<=2 iterations) ----------------
    while (g0 < gEnd) {
        const int t = g0 / CPT;                       // m-tile
        const int seg_end = min(gEnd, (t + 1) * CPT);
        const int nch = seg_end - g0;
        const int kbase = g0 - t * CPT;               // first chunk within tile
        const int ordinal = cta - (t * CPT) / WCHUNK; // partial slot, 0..5

        const float* Xb = (t < 16) ? (wf + (size_t)t * 128 * KDIM)
                                   : (bfeat + (size_t)(t - 16) * 128 * KDIM);
        const float* pA0 = Xb + (size_t)pr * KDIM + pc * 4;

        #pragma unroll
        for (int i = 0; i < 2; i++)
            #pragma unroll
            for (int tt = 0; tt < 8; tt++)
                #pragma unroll
                for (int q = 0; q < 4; q++) acc[i][tt][q] = 0.0f;

        // prologue: fill stage 0 with chunk kbase
        {
            size_t k = (size_t)kbase * BK;
            #pragma unroll
            for (int q = 0; q < 4; q++)
                *(uint2*)(smem + sA0 + q * 32 * PITCH_U) = cvt4h(*(const float4*)(pA0 + q * QSTEP + k));
            #pragma unroll
            for (int q = 0; q < 8; q++)
                *(uint2*)(smem + sB0 + q * 32 * PITCH_U) = cvt4h(*(const float4*)(pB0 + q * QSTEP + k));
        }
        __syncthreads();

        for (int l = 0; l < nch; l++) {
            const int buf = l & 1;
            const bool more = (l + 1 < nch);
            const uint32_t stOff = (uint32_t)buf * STAGE_BYTES;
            const uint32_t nbU32 = (uint32_t)(buf ^ 1) * STAGE_U32;
            const size_t k2 = (size_t)(kbase + l + 1) * BK;

            // batch 1: A(4) + B(q=0,1) loads for next chunk
            float4 v0, v1, v2, v3, v4, v5;
            if (more) {
                v0 = *(const float4*)(pA0 + 0 * QSTEP + k2);
                v1 = *(const float4*)(pA0 + 1 * QSTEP + k2);
                v2 = *(const float4*)(pA0 + 2 * QSTEP + k2);
                v3 = *(const float4*)(pA0 + 3 * QSTEP + k2);
                v4 = *(const float4*)(pB0 + 0 * QSTEP + k2);
                v5 = *(const float4*)(pB0 + 1 * QSTEP + k2);
            }

            #pragma unroll
            for (int jp = 0; jp < 2; jp++) {     // 2 k-step pairs (each 32 f16)
                uint32_t aF[2][2][4];
                #pragma unroll
                for (int i = 0; i < 2; i++)
                    #pragma unroll
                    for (int js = 0; js < 2; js++)
                        ldsm_x4(aF[i][js], aAddr + stOff
                                + (uint32_t)(i * 16 * PITCH_BY + jp * 64 + js * 32));

                uint32_t bF[2][4];
                ldsm_x4(bF[0], bAddr + stOff + (uint32_t)(jp * 64));
                #pragma unroll
                for (int tt = 0; tt < 8; tt++) {
                    if (tt < 7)
                        ldsm_x4(bF[(tt + 1) & 1], bAddr + stOff
                                + (uint32_t)((tt + 1) * 8 * PITCH_BY + jp * 64));
                    const uint32_t* bf = bF[tt & 1];
                    mma_f16(acc[0][tt], aF[0][0], bf);       // k-step 2jp
                    mma_f16(acc[1][tt], aF[1][0], bf);
                    mma_f16(acc[0][tt], aF[0][1], bf + 2);   // k-step 2jp+1
                    mma_f16(acc[1][tt], aF[1][1], bf + 2);
                }

                if (jp == 0 && more) {
                    *(uint2*)(smem + nbU32 + sA0 + 0 * 32 * PITCH_U) = cvt4h(v0);
                    *(uint2*)(smem + nbU32 + sA0 + 1 * 32 * PITCH_U) = cvt4h(v1);
                    *(uint2*)(smem + nbU32 + sA0 + 2 * 32 * PITCH_U) = cvt4h(v2);
                    *(uint2*)(smem + nbU32 + sA0 + 3 * 32 * PITCH_U) = cvt4h(v3);
                    *(uint2*)(smem + nbU32 + sB0 + 0 * 32 * PITCH_U) = cvt4h(v4);
                    *(uint2*)(smem + nbU32 + sB0 + 1 * 32 * PITCH_U) = cvt4h(v5);
                    v0 = *(const float4*)(pB0 + 2 * QSTEP + k2);
                    v1 = *(const float4*)(pB0 + 3 * QSTEP + k2);
                    v2 = *(const float4*)(pB0 + 4 * QSTEP + k2);
                    v3 = *(const float4*)(pB0 + 5 * QSTEP + k2);
                    v4 = *(const float4*)(pB0 + 6 * QSTEP + k2);
                    v5 = *(const float4*)(pB0 + 7 * QSTEP + k2);
                }
            }

            if (more) {
                *(uint2*)(smem + nbU32 + sB0 + 2 * 32 * PITCH_U) = cvt4h(v0);
                *(uint2*)(smem + nbU32 + sB0 + 3 * 32 * PITCH_U) = cvt4h(v1);
                *(uint2*)(smem + nbU32 + sB0 + 4 * 32 * PITCH_U) = cvt4h(v2);
                *(uint2*)(smem + nbU32 + sB0 + 5 * 32 * PITCH_U) = cvt4h(v3);
                *(uint2*)(smem + nbU32 + sB0 + 6 * 32 * PITCH_U) = cvt4h(v4);
                *(uint2*)(smem + nbU32 + sB0 + 7 * 32 * PITCH_U) = cvt4h(v5);
            }
            __syncthreads();
        }

        // ------ flush partial for this segment ------
        float* op = g_part + ((size_t)ordinal * MTOT + (size_t)t * 128) * NHID;
        #pragma unroll
        for (int i = 0; i < 2; i++) {
            #pragma unroll
            for (int tt = 0; tt < 8; tt++) {
                int row = mw + i * 16 + lr;
                int col = nw + tt * 8 + 2 * lc;
                float2 w0 = make_float2(acc[i][tt][0], acc[i][tt][1]);
                float2 w1 = make_float2(acc[i][tt][2], acc[i][tt][3]);
                *(float2*)(op + (size_t)row * NHID + col) = w0;
                *(float2*)(op + (size_t)(row + 8) * NHID + col) = w1;
            }
        }

        g0 = seg_end;
    }
}

// =====================================================================
// Kernel 2: fixed 6-slot reduce + bias + relu + 3-layer MLP tail
// 256 blocks x 512 threads, 8 batch rows per block.
// Layer 1 split: warp w -> row (w&7), j-half (w>>3); partials combined
// through smem. smem ~91KB -> 2 blocks/SM co-resident.
// =====================================================================
__global__ void __launch_bounds__(512) nnue_tail(
    const float* __restrict__ b_in,
    const float* __restrict__ W_h1, const float* __restrict__ b_h1,
    const float* __restrict__ W_h2, const float* __restrict__ b_h2,
    const float* __restrict__ W_out, const float* __restrict__ b_out,
    float* __restrict__ out)
{
    extern __shared__ float smem_t[];
    float* Wh1T = smem_t;                    // [512][33]
    float* c_sm = Wh1T + 512 * 33;           // [8][512]
    float* Wh2T = c_sm + 8 * 512;            // [32][33]
    float* x1p  = Wh2T + 32 * 33;            // [16][32] layer-1 partials
    float* x1s  = x1p + 16 * 32;             // [8][32]

    const int tid = threadIdx.x;
    const int row0 = blockIdx.x * 8;         // 0..2040

    for (int i = tid; i < 512 * 32; i += 512) {
        int o = i >> 9, j = i & 511;
        Wh1T[j * 33 + o] = W_h1[i];
    }
    for (int i = tid; i < 32 * 32; i += 512) {   // 1024 elems, 2 iters
        int o = i >> 5, j = i & 31;
        Wh2T[j * 33 + o] = W_h2[i];
    }
    // combined = [relu(wh), relu(bh)]: fixed 6-slot reduce (unwritten slots
    // are guaranteed-zero __device__ memory) -> 6 independent loads in flight
    for (int e = tid; e < 8 * 512; e += 512) {
        int rs = e >> 9, j = e & 511;
        int col = j & 255;
        int m = (j < 256) ? (row0 + rs) : (2048 + row0 + rs);
        size_t base = (size_t)m * NHID + col;
        float p0 = g_part[0 * (size_t)MTOT * NHID + base];
        float p1 = g_part[1 * (size_t)MTOT * NHID + base];
        float p2 = g_part[2 * (size_t)MTOT * NHID + base];
        float p3 = g_part[3 * (size_t)MTOT * NHID + base];
        float p4 = g_part[4 * (size_t)MTOT * NHID + base];
        float p5 = g_part[5 * (size_t)MTOT * NHID + base];
        float v = b_in[col] + ((p0 + p1) + (p2 + p3)) + (p4 + p5);
        c_sm[e] = fmaxf(v, 0.0f);
    }
    __syncthreads();

    const int o    = tid & 31;
    const int w    = tid >> 5;       // 0..15
    const int r    = w & 7;          // batch row within block
    const int half = w >> 3;         // j-range half: 0 or 1

    // layer 1 (split): 256 js per warp, c loads vectorized
    {
        float a0 = 0.f, a1 = 0.f, a2 = 0.f, a3 = 0.f;
        const float* c = c_sm + r * 512 + half * 256;
        #pragma unroll 2
        for (int j = 0; j < 256; j += 4) {
            float4 cv = *(const float4*)(c + j);
            int jw = half * 256 + j;
            a0 = fmaf(cv.x, Wh1T[(jw + 0) * 33 + o], a0);
            a1 = fmaf(cv.y, Wh1T[(jw + 1) * 33 + o], a1);
            a2 = fmaf(cv.z, Wh1T[(jw + 2) * 33 + o], a2);
            a3 = fmaf(cv.w, Wh1T[(jw + 3) * 33 + o], a3);
        }
        x1p[(half * 8 + r) * 32 + o] = (a0 + a1) + (a2 + a3);
    }
    __syncthreads();

    if (w < 8) {   // warps 0-7: combine halves, layer 2, output
        float x1 = fmaxf(x1p[r * 32 + o] + x1p[(8 + r) * 32 + o] + b_h1[o], 0.0f);
        x1s[r * 32 + o] = x1;
        __syncwarp();

        // layer 2: [32, 32]
        float acc2 = b_h2[o];
        #pragma unroll
        for (int j = 0; j < 32; j++)
            acc2 = fmaf(x1s[r * 32 + j], Wh2T[j * 33 + o], acc2);
        float x2 = fmaxf(acc2, 0.0f);

        // output: dot + warp reduce
        float y = x2 * W_out[o];
        #pragma unroll
        for (int d = 16; d > 0; d >>= 1)
            y += __shfl_xor_sync(0xFFFFFFFF, y, d);
        if (o == 0)
            out[row0 + r] = y + b_out[0];
    }
}

// =====================================================================
extern "C" void kernel_launch(void* const* d_in, const int* in_sizes, int n_in,
                              void* d_out, int out_size) {
    const float* wf    = (const float*)d_in[0];
    const float* bfeat = (const float*)d_in[1];
    const float* W_in  = (const float*)d_in[2];
    const float* b_in  = (const float*)d_in[3];
    const float* W_h1  = (const float*)d_in[4];
    const float* b_h1  = (const float*)d_in[5];
    const float* W_h2  = (const float*)d_in[6];
    const float* b_h2  = (const float*)d_in[7];
    const float* W_out = (const float*)d_in[8];
    const float* b_out = (const float*)d_in[9];
    float* out = (float*)d_out;

    cudaFuncSetAttribute(nnue_gemm, cudaFuncAttributeMaxDynamicSharedMemorySize, GEMM_SMEM);
    cudaFuncSetAttribute(nnue_tail, cudaFuncAttributeMaxDynamicSharedMemorySize, TAIL_SMEM);

    nnue_gemm<<<NCTAS, 512, GEMM_SMEM>>>(wf, bfeat, W_in);
    nnue_tail<<<256, 512, TAIL_SMEM>>>(b_in, W_h1, b_h1, W_h2, b_h2, W_out, b_out, out);
}